// round 9
// baseline (speedup 1.0000x reference)
#include <cuda_runtime.h>
#include <math.h>

// ARIMA sliding-window loss, algebraically collapsed to:
//   err[t] = y[t+33] - K1*FIR(g, win) + M1q*sum - K2q*sqrt(32*sq - sum^2 + 1024*eps)
//   loss   = (sum(y[:33]^2) + sum(err^2)) / S
// Two-phase FIR: taps 0-15 over xv[0..23], then taps 16-31 over xv[16..43].
// Peak live window = 28 floats -> whole working set stays in registers
// (no in-loop LDS re-reads). Swizzled smem staging, single-wave grid.

#define PW    32
#define T0    33
#define EPSF  1e-5f
#define TPB   128
#define RPT   8
#define TILE  (TPB * RPT)        // 1024 t per block
#define STAGE 1088
#define MAXB  2048

#define SWZ(b) ((b) ^ (((b) >> 3) & 0x70))

__device__ double       g_part[MAXB];
__device__ unsigned int g_ctr = 0;   // atomicInc wraps to 0 each launch

__device__ __forceinline__ float sqrt_apx(float x) {
    float r; asm("sqrt.approx.f32 %0, %1;" : "=f"(r) : "f"(x)); return r;
}

__global__ void __launch_bounds__(TPB, 7) arima_fused(
    const float* __restrict__ y,
    const float* __restrict__ w,
    const float* __restrict__ ab,
    const float* __restrict__ rw_,
    const float* __restrict__ rb_,
    float* __restrict__ out,
    int T, int S)
{
    __shared__ __align__(128) float sy[STAGE];   // swizzled y[tb .. tb+1068)
    __shared__ __align__(16)  float sg[PW];
    __shared__ float  sc[3];
    __shared__ double sred[TPB / 32];
    __shared__ int    isLast;

    const float4* sg4 = (const float4*)sg;
    const int tid = threadIdx.x;
    const int bid = blockIdx.x;
    const int tb  = bid * TILE;

    // FIR taps from ar_weight + differencing structure
    if (tid < PW) {
        float wj  = w[tid];
        float wj1 = (tid < PW - 1) ? w[tid + 1] : 0.0f;
        float gv  = wj - wj1;
        if (tid == PW - 2) gv -= 1.0f;   // g[30] = w30 - w31 - 1
        if (tid == PW - 1) gv += 1.0f;   // g[31] = w31 + 1
        sg[tid] = gv;
    }
    if (tid == 0) {
        float rw = rw_[0], rb = rb_[0], b = ab[0], w0 = w[0];
        float denom = rw + EPSF * EPSF;
        float K1 = rw / denom;
        float K2 = (w0 * rb - rb + b) / denom;
        float M1 = fmaf(K1, w0, -1.0f);
        sc[0] = K1;
        sc[1] = K2 * (1.0f / 32.0f);      // K2q
        sc[2] = M1 * (1.0f / 32.0f);      // M1q
    }

    // Coalesced stage, swizzled store: chunk i holds y[tb+4i .. +3]
    {
        const float4* y4 = (const float4*)(y + tb);
        #pragma unroll
        for (int c = 0; c < 3; c++) {
            int i = tid + c * TPB;
            if (i < 267) {
                int gf = tb + 4 * i;
                float4 v;
                if (gf + 3 < S) v = y4[i];
                else {
                    v.x = (gf     < S) ? y[gf]     : 0.f;
                    v.y = (gf + 1 < S) ? y[gf + 1] : 0.f;
                    v.z = (gf + 2 < S) ? y[gf + 2] : 0.f;
                    v.w = (gf + 3 < S) ? y[gf + 3] : 0.f;
                }
                *(float4*)((char*)sy + SWZ(16 * i)) = v;
            }
        }
    }
    __syncthreads();

    const float K1 = sc[0], K2q = sc[1], M1q = sc[2];
    const float C0 = 1024.0f * EPSF;
    const int t0 = tb + tid * RPT;       // xv[m] = y[t0+m]

    float f[RPT];
    #pragma unroll
    for (int r = 0; r < RPT; r++) f[r] = 0.0f;
    float sum = 0.f, sq = 0.f;
    float old[RPT];                      // xv[0..7], kept for the sliding epilogue

    // ---- Phase A: xv[0..23], taps j = 0..15 ----
    {
        float xa[24];
        #pragma unroll
        for (int c = 0; c < 6; c++) {
            int k = 2 * tid + c;
            float4 v = *(const float4*)((const char*)sy + SWZ(16 * k));
            xa[4*c + 0] = v.x; xa[4*c + 1] = v.y;
            xa[4*c + 2] = v.z; xa[4*c + 3] = v.w;
        }
        #pragma unroll
        for (int r = 0; r < RPT; r++) old[r] = xa[r];

        #pragma unroll
        for (int c = 0; c < 4; c++) {
            float4 gc = sg4[c];
            const float ge[4] = {gc.x, gc.y, gc.z, gc.w};
            #pragma unroll
            for (int e = 0; e < 4; e++) {
                const int j = 4 * c + e;          // 0..15
                float xj = xa[1 + j];
                sum += xj;
                sq   = fmaf(xj, xj, sq);
                #pragma unroll
                for (int r = 0; r < RPT; r++)     // reads xa[1..23]
                    f[r] = fmaf(ge[e], xa[1 + j + r], f[r]);
            }
        }
        // finish sum/sq over xa[17..23] (xv[17..23]) — not covered below
        #pragma unroll
        for (int m = 17; m < 24; m++) {
            sum += xa[m];
            sq   = fmaf(xa[m], xa[m], sq);
        }
    }

    // ---- Phase B: xv[16..43], taps j = 16..31, epilogue ----
    float esum_f = 0.0f;
    {
        float xb[28];                    // xb[i] = xv[16+i]
        #pragma unroll
        for (int c = 0; c < 7; c++) {
            int k = 2 * tid + 4 + c;
            float4 v = *(const float4*)((const char*)sy + SWZ(16 * k));
            xb[4*c + 0] = v.x; xb[4*c + 1] = v.y;
            xb[4*c + 2] = v.z; xb[4*c + 3] = v.w;
        }

        #pragma unroll
        for (int c = 4; c < 8; c++) {
            float4 gc = sg4[c];
            const float ge[4] = {gc.x, gc.y, gc.z, gc.w};
            #pragma unroll
            for (int e = 0; e < 4; e++) {
                const int j = 4 * c + e;          // 16..31
                #pragma unroll
                for (int r = 0; r < RPT; r++)     // xv[17..39] -> xb[1..23]
                    f[r] = fmaf(ge[e], xb[j + r - 15], f[r]);
            }
        }
        // sum/sq over xv[24..32] = xb[8..16]
        #pragma unroll
        for (int m = 8; m <= 16; m++) {
            sum += xb[m];
            sq   = fmaf(xb[m], xb[m], sq);
        }
        // now sum/sq cover xv[1..32] (window of t0)

        if (t0 + RPT <= T) {             // interior fast path
            #pragma unroll
            for (int r = 0; r < RPT; r++) {
                if (r > 0) {
                    float xn = xb[16 + r], xo = old[r];   // xv[32+r], xv[r]
                    sum += xn - xo;
                    sq   = fmaf(xn, xn, sq);
                    sq   = fmaf(-xo, xo, sq);
                }
                float u   = fmaf(-sum, sum, 32.0f * sq);
                float sd  = sqrt_apx(u + C0);
                float err = fmaf(-K2q, sd, fmaf(M1q, sum, fmaf(-K1, f[r], xb[17 + r])));
                esum_f = fmaf(err, err, esum_f);
            }
        } else {
            #pragma unroll
            for (int r = 0; r < RPT; r++) {
                if (r > 0) {
                    float xn = xb[16 + r], xo = old[r];
                    sum += xn - xo;
                    sq   = fmaf(xn, xn, sq);
                    sq   = fmaf(-xo, xo, sq);
                }
                if (t0 + r < T) {
                    float u   = fmaf(-sum, sum, 32.0f * sq);
                    float sd  = sqrt_apx(u + C0);
                    float err = fmaf(-K2q, sd, fmaf(M1q, sum, fmaf(-K1, f[r], xb[17 + r])));
                    esum_f = fmaf(err, err, esum_f);
                }
            }
        }
    }

    // Block reduction (double from warp level up)
    double esum = (double)esum_f;
    #pragma unroll
    for (int o = 16; o > 0; o >>= 1)
        esum += __shfl_down_sync(0xffffffffu, esum, o);
    if ((tid & 31) == 0) sred[tid >> 5] = esum;
    __syncthreads();
    if (tid == 0) {
        double bs = 0.0;
        #pragma unroll
        for (int i = 0; i < TPB / 32; i++) bs += sred[i];
        g_part[bid] = bs;
        __threadfence();
        unsigned pos = atomicInc(&g_ctr, gridDim.x - 1);
        isLast = (pos == gridDim.x - 1);
    }
    __syncthreads();

    // Last block: deterministic final reduction + head term
    if (isLast) {
        __threadfence();
        double s = 0.0;
        for (int i = tid; i < (int)gridDim.x; i += TPB) s += g_part[i];
        for (int i = tid; i < T0; i += TPB) { double v = (double)y[i]; s += v * v; }
        #pragma unroll
        for (int o = 16; o > 0; o >>= 1)
            s += __shfl_down_sync(0xffffffffu, s, o);
        if ((tid & 31) == 0) sred[tid >> 5] = s;
        __syncthreads();
        if (tid == 0) {
            double tot = 0.0;
            #pragma unroll
            for (int i = 0; i < TPB / 32; i++) tot += sred[i];
            out[0] = (float)(tot / (double)S);
        }
    }
}

extern "C" void kernel_launch(void* const* d_in, const int* in_sizes, int n_in,
                              void* d_out, int out_size)
{
    const float* y  = (const float*)d_in[0];
    const float* w  = (const float*)d_in[1];
    const float* ab = (const float*)d_in[2];
    const float* rw = (const float*)d_in[3];
    const float* rb = (const float*)d_in[4];
    int S = in_sizes[0];
    int T = S - T0;
    int nblocks = (T + TILE - 1) / TILE;   // S=1M -> 1024 blocks, single wave
    if (nblocks > MAXB) nblocks = MAXB;
    arima_fused<<<nblocks, TPB>>>(y, w, ab, rw, rb, (float*)d_out, T, S);
}

// round 10
// speedup vs baseline: 1.0025x; 1.0025x over previous
#include <cuda_runtime.h>
#include <math.h>

// ARIMA sliding-window loss, algebraically collapsed to:
//   err[t] = y[t+33] - K1*FIR(g, win) + M1q*sum - K2q*sqrt(32*sq - sum^2 + 1024*eps)
//   loss   = (sum(y[:33]^2) + sum(err^2)) / S
// RPT=16, four 8-tap FIR phases (24-float live window per phase), TPB=64 with
// an 8-CTA/SM launch bound -> 128-reg budget, fully register-resident.
// Swizzled smem staging keeps the 64B-stride window LDS.128 conflict-free.

#define PW    32
#define T0    33
#define EPSF  1e-5f
#define TPB   64
#define RPT   16
#define TILE  (TPB * RPT)        // 1024 t per block
#define STAGE 1088               // floats; need y[tb .. tb+1056], padded
#define NCHUNK 265               // ceil(1060/4): chunks 0..264 cover floats 0..1059
#define MAXB  2048

#define SWZ(b) ((b) ^ (((b) >> 3) & 0x70))

__device__ double       g_part[MAXB];
__device__ unsigned int g_ctr = 0;   // atomicInc wraps to 0 each launch

__device__ __forceinline__ float sqrt_apx(float x) {
    float r; asm("sqrt.approx.f32 %0, %1;" : "=f"(r) : "f"(x)); return r;
}

__global__ void __launch_bounds__(TPB, 8) arima_fused(
    const float* __restrict__ y,
    const float* __restrict__ w,
    const float* __restrict__ ab,
    const float* __restrict__ rw_,
    const float* __restrict__ rb_,
    float* __restrict__ out,
    int T, int S)
{
    __shared__ __align__(128) float sy[STAGE];   // swizzled y[tb + i]
    __shared__ __align__(16)  float sg[PW];
    __shared__ float  sc[3];
    __shared__ double sred[TPB / 32];
    __shared__ int    isLast;

    const float4* sg4 = (const float4*)sg;
    const int tid = threadIdx.x;
    const int bid = blockIdx.x;
    const int tb  = bid * TILE;

    // FIR taps from ar_weight + differencing structure
    if (tid < PW) {
        float wj  = w[tid];
        float wj1 = (tid < PW - 1) ? w[tid + 1] : 0.0f;
        float gv  = wj - wj1;
        if (tid == PW - 2) gv -= 1.0f;   // g[30] = w30 - w31 - 1
        if (tid == PW - 1) gv += 1.0f;   // g[31] = w31 + 1
        sg[tid] = gv;
    }
    if (tid == 0) {
        float rw = rw_[0], rb = rb_[0], b = ab[0], w0 = w[0];
        float denom = rw + EPSF * EPSF;
        float K1 = rw / denom;
        float K2 = (w0 * rb - rb + b) / denom;
        float M1 = fmaf(K1, w0, -1.0f);
        sc[0] = K1;
        sc[1] = K2 * (1.0f / 32.0f);      // K2q
        sc[2] = M1 * (1.0f / 32.0f);      // M1q
    }

    // Coalesced stage, swizzled store: chunk i holds y[tb+4i .. +3]
    {
        const float4* y4 = (const float4*)(y + tb);
        #pragma unroll
        for (int c = 0; c < 5; c++) {
            int i = tid + c * TPB;
            if (i < NCHUNK) {
                int gf = tb + 4 * i;
                float4 v;
                if (gf + 3 < S) v = y4[i];
                else {
                    v.x = (gf     < S) ? y[gf]     : 0.f;
                    v.y = (gf + 1 < S) ? y[gf + 1] : 0.f;
                    v.z = (gf + 2 < S) ? y[gf + 2] : 0.f;
                    v.w = (gf + 3 < S) ? y[gf + 3] : 0.f;
                }
                *(float4*)((char*)sy + SWZ(16 * i)) = v;
            }
        }
    }
    __syncthreads();

    const float K1 = sc[0], K2q = sc[1], M1q = sc[2];
    const float C0 = 1024.0f * EPSF;
    const int t0 = tb + tid * RPT;       // xv[m] = y[t0+m] = sy-chunk (4*tid + m/4)

    float f[RPT];
    #pragma unroll
    for (int r = 0; r < RPT; r++) f[r] = 0.0f;
    float sum = 0.f, sq = 0.f;
    float old_[RPT];                     // xv[0..15]
    float tail[RPT + 1];                 // tail[i] = xv[32+i], i in [0,16]

    // Four phases: phase p covers taps j = 8p..8p+7 over xv[8p .. 8p+23]
    #pragma unroll
    for (int p = 0; p < 4; p++) {
        float xp[24];                    // xp[i] = xv[8p + i]
        #pragma unroll
        for (int c = 0; c < 6; c++) {
            int k = 4 * tid + 2 * p + c;
            float4 v = *(const float4*)((const char*)sy + SWZ(16 * k));
            xp[4*c + 0] = v.x; xp[4*c + 1] = v.y;
            xp[4*c + 2] = v.z; xp[4*c + 3] = v.w;
        }
        if (p == 0) {
            #pragma unroll
            for (int i = 0; i < RPT; i++) old_[i] = xp[i];
            #pragma unroll
            for (int m = 1; m < 24; m++) {       // xv[1..23]
                sum += xp[m];
                sq   = fmaf(xp[m], xp[m], sq);
            }
        }
        if (p == 3) {
            #pragma unroll
            for (int i = 0; i < RPT; i++) tail[i] = xp[8 + i];
            #pragma unroll
            for (int m = 0; m <= 8; m++) {       // xv[24..32]
                sum += xp[m];
                sq   = fmaf(xp[m], xp[m], sq);
            }
        }
        #pragma unroll
        for (int cc = 0; cc < 2; cc++) {
            float4 gc = sg4[2 * p + cc];
            const float ge[4] = {gc.x, gc.y, gc.z, gc.w};
            #pragma unroll
            for (int e = 0; e < 4; e++) {
                const int jp = 4 * cc + e;       // j' in [0,8)
                #pragma unroll
                for (int r = 0; r < RPT; r++)
                    f[r] = fmaf(ge[e], xp[1 + r + jp], f[r]);
            }
        }
    }
    {   // tail[16] = xv[48]
        int k = 4 * tid + 12;
        float4 v = *(const float4*)((const char*)sy + SWZ(16 * k));
        tail[16] = v.x;
    }

    // Epilogue: sum/sq now cover xv[1..32] (window of t0)
    float esum_f = 0.0f;
    if (t0 + RPT <= T) {                 // interior fast path
        #pragma unroll
        for (int r = 0; r < RPT; r++) {
            if (r > 0) {
                float xn = tail[r], xo = old_[r];
                sum += xn - xo;
                sq   = fmaf(xn, xn, sq);
                sq   = fmaf(-xo, xo, sq);
            }
            float u   = fmaf(-sum, sum, 32.0f * sq);
            float sd  = sqrt_apx(u + C0);
            float err = fmaf(-K2q, sd, fmaf(M1q, sum, fmaf(-K1, f[r], tail[r + 1])));
            esum_f = fmaf(err, err, esum_f);
        }
    } else {
        #pragma unroll
        for (int r = 0; r < RPT; r++) {
            if (r > 0) {
                float xn = tail[r], xo = old_[r];
                sum += xn - xo;
                sq   = fmaf(xn, xn, sq);
                sq   = fmaf(-xo, xo, sq);
            }
            if (t0 + r < T) {
                float u   = fmaf(-sum, sum, 32.0f * sq);
                float sd  = sqrt_apx(u + C0);
                float err = fmaf(-K2q, sd, fmaf(M1q, sum, fmaf(-K1, f[r], tail[r + 1])));
                esum_f = fmaf(err, err, esum_f);
            }
        }
    }

    // Block reduction (double from warp level up)
    double esum = (double)esum_f;
    #pragma unroll
    for (int o = 16; o > 0; o >>= 1)
        esum += __shfl_down_sync(0xffffffffu, esum, o);
    if ((tid & 31) == 0) sred[tid >> 5] = esum;
    __syncthreads();
    if (tid == 0) {
        double bs = sred[0] + sred[1];
        g_part[bid] = bs;
        __threadfence();
        unsigned pos = atomicInc(&g_ctr, gridDim.x - 1);
        isLast = (pos == gridDim.x - 1);
    }
    __syncthreads();

    // Last block: deterministic final reduction + head term
    if (isLast) {
        __threadfence();
        double s = 0.0;
        for (int i = tid; i < (int)gridDim.x; i += TPB) s += g_part[i];
        for (int i = tid; i < T0; i += TPB) { double v = (double)y[i]; s += v * v; }
        #pragma unroll
        for (int o = 16; o > 0; o >>= 1)
            s += __shfl_down_sync(0xffffffffu, s, o);
        if ((tid & 31) == 0) sred[tid >> 5] = s;
        __syncthreads();
        if (tid == 0)
            out[0] = (float)((sred[0] + sred[1]) / (double)S);
    }
}

extern "C" void kernel_launch(void* const* d_in, const int* in_sizes, int n_in,
                              void* d_out, int out_size)
{
    const float* y  = (const float*)d_in[0];
    const float* w  = (const float*)d_in[1];
    const float* ab = (const float*)d_in[2];
    const float* rw = (const float*)d_in[3];
    const float* rb = (const float*)d_in[4];
    int S = in_sizes[0];
    int T = S - T0;
    int nblocks = (T + TILE - 1) / TILE;   // S=1M -> 1024 blocks, single wave
    if (nblocks > MAXB) nblocks = MAXB;
    arima_fused<<<nblocks, TPB>>>(y, w, ab, rw, rb, (float*)d_out, T, S);
}